// round 1
// baseline (speedup 1.0000x reference)
#include <cuda_runtime.h>
#include <cstddef>

#define TGT 256
#define BSZ 8
#define EDIM 256
#define SRCL 4096

// Scratch for pre-projection result X[b][t][e]  (2 MB)
__device__ float g_O[BSZ * TGT * EDIM];

// -------------------------------------------------------------------------
// attn_weights output == proposal_mask, verbatim. Vectorized copy.
// -------------------------------------------------------------------------
__global__ __launch_bounds__(256) void copy_mask_kernel(const float4* __restrict__ src,
                                                        float4* __restrict__ dst) {
    int i = blockIdx.x * 256 + threadIdx.x;
    dst[i] = src[i];
}

// -------------------------------------------------------------------------
// GEMM1: X_b = mask_b [256 x 4096] @ value[:,b,:] [4096 x 256]
// Block: 64x64 C-tile, 256 threads, 4x4 per thread, BK=16.
// As stored transposed [k][m] so a-frag is a float4 LDS.
// -------------------------------------------------------------------------
__global__ __launch_bounds__(256) void gemm1_kernel(const float* __restrict__ mask,
                                                    const float* __restrict__ value) {
    const int b  = blockIdx.z;
    const int m0 = blockIdx.y * 64;
    const int n0 = blockIdx.x * 64;
    const int t  = threadIdx.x;
    const int tx = t & 15, ty = t >> 4;

    __shared__ float As[16][68];   // [k][m], stride 68 keeps float4 alignment
    __shared__ float Bs[16][68];   // [k][n]

    const float* Ag = mask  + ((size_t)b * TGT + m0) * SRCL;
    const float* Bg = value + (size_t)b * EDIM + n0;

    const int ar = t >> 2;          // 0..63  m-row
    const int ac = (t & 3) << 2;    // k col4
    const int br = t >> 4;          // 0..15  k-row
    const int bc = (t & 15) << 2;   // n col4

    float acc[4][4] = {};

    for (int k0 = 0; k0 < SRCL; k0 += 16) {
        float4 av = *(const float4*)(Ag + (size_t)ar * SRCL + k0 + ac);
        float4 bv = *(const float4*)(Bg + (size_t)(k0 + br) * (BSZ * EDIM) + bc);
        __syncthreads();
        As[ac + 0][ar] = av.x;
        As[ac + 1][ar] = av.y;
        As[ac + 2][ar] = av.z;
        As[ac + 3][ar] = av.w;
        *(float4*)&Bs[br][bc] = bv;
        __syncthreads();
#pragma unroll
        for (int kk = 0; kk < 16; kk++) {
            float4 a4 = *(const float4*)&As[kk][ty << 2];
            float4 b4 = *(const float4*)&Bs[kk][tx << 2];
            float af[4] = {a4.x, a4.y, a4.z, a4.w};
            float bf[4] = {b4.x, b4.y, b4.z, b4.w};
#pragma unroll
            for (int i = 0; i < 4; i++)
#pragma unroll
                for (int j = 0; j < 4; j++)
                    acc[i][j] += af[i] * bf[j];
        }
    }

    float* Op = g_O + ((size_t)b * TGT + m0 + (ty << 2)) * EDIM + n0 + (tx << 2);
#pragma unroll
    for (int i = 0; i < 4; i++) {
        float4 v4 = make_float4(acc[i][0], acc[i][1], acc[i][2], acc[i][3]);
        *(float4*)(Op + (size_t)i * EDIM) = v4;
    }
}

// -------------------------------------------------------------------------
// GEMM2: out[t,b,:] = X_b[t,:] @ W^T + bias     (K = 256)
// Same tiling; W is row-major [E][E], we need B[k][e] = W[e][k], so store
// transposed into Bs exactly like As.
// -------------------------------------------------------------------------
__global__ __launch_bounds__(256) void gemm2_kernel(const float* __restrict__ W,
                                                    const float* __restrict__ bias,
                                                    float* __restrict__ out) {
    const int b  = blockIdx.z;
    const int m0 = blockIdx.y * 64;
    const int n0 = blockIdx.x * 64;
    const int t  = threadIdx.x;
    const int tx = t & 15, ty = t >> 4;

    __shared__ float As[16][68];   // [k][m]
    __shared__ float Bs[16][68];   // [k][e]

    const float* Ag = g_O + ((size_t)b * TGT + m0) * EDIM;
    const float* Bg = W + (size_t)n0 * EDIM;

    const int ar = t >> 2;          // 0..63 row (m for A, e for B)
    const int ac = (t & 3) << 2;    // k col4

    float acc[4][4] = {};

    for (int k0 = 0; k0 < EDIM; k0 += 16) {
        float4 av = *(const float4*)(Ag + (size_t)ar * EDIM + k0 + ac);
        float4 bv = *(const float4*)(Bg + (size_t)ar * EDIM + k0 + ac);
        __syncthreads();
        As[ac + 0][ar] = av.x;
        As[ac + 1][ar] = av.y;
        As[ac + 2][ar] = av.z;
        As[ac + 3][ar] = av.w;
        Bs[ac + 0][ar] = bv.x;
        Bs[ac + 1][ar] = bv.y;
        Bs[ac + 2][ar] = bv.z;
        Bs[ac + 3][ar] = bv.w;
        __syncthreads();
#pragma unroll
        for (int kk = 0; kk < 16; kk++) {
            float4 a4 = *(const float4*)&As[kk][ty << 2];
            float4 b4 = *(const float4*)&Bs[kk][tx << 2];
            float af[4] = {a4.x, a4.y, a4.z, a4.w};
            float bf[4] = {b4.x, b4.y, b4.z, b4.w};
#pragma unroll
            for (int i = 0; i < 4; i++)
#pragma unroll
                for (int j = 0; j < 4; j++)
                    acc[i][j] += af[i] * bf[j];
        }
    }

    float4 bias4 = *(const float4*)(bias + n0 + (tx << 2));
#pragma unroll
    for (int i = 0; i < 4; i++) {
        int row = m0 + (ty << 2) + i;
        float4 v4 = make_float4(acc[i][0] + bias4.x,
                                acc[i][1] + bias4.y,
                                acc[i][2] + bias4.z,
                                acc[i][3] + bias4.w);
        *(float4*)(out + ((size_t)row * BSZ + b) * EDIM + n0 + (tx << 2)) = v4;
    }
}

// -------------------------------------------------------------------------
// Launch: inputs are [query, key, value, proposal_mask, out_proj_weight,
// out_proj_bias]; output is attn_output (256*8*256 floats) followed by
// attn_weights (8*256*4096 floats).
// -------------------------------------------------------------------------
extern "C" void kernel_launch(void* const* d_in, const int* in_sizes, int n_in,
                              void* d_out, int out_size) {
    const float* value = (const float*)d_in[2];
    const float* mask  = (const float*)d_in[3];
    const float* W     = (const float*)d_in[4];
    const float* bias  = (const float*)d_in[5];
    float* out = (float*)d_out;

    float* attn_out = out;                                  // (TGT, BSZ, E)
    float* weights  = out + (size_t)TGT * BSZ * EDIM;       // (BSZ, TGT, SRC)

    // 1) attn_weights = proposal_mask  (33.5 MB copy)
    {
        int n4 = (BSZ * TGT * SRCL) / 4;                    // 2097152
        copy_mask_kernel<<<n4 / 256, 256>>>((const float4*)mask, (float4*)weights);
    }

    // 2) X_b = mask_b @ value_b
    {
        float* gO = nullptr;
        cudaGetSymbolAddress((void**)&gO, g_O);
        dim3 grid(4, 4, BSZ);
        gemm1_kernel<<<grid, 256>>>(mask, value);
    }

    // 3) out = X @ W^T + bias
    {
        dim3 grid(4, 4, BSZ);
        gemm2_kernel<<<grid, 256>>>(W, bias, attn_out);
    }
}

// round 4
// speedup vs baseline: 3.0511x; 3.0511x over previous
#include <cuda_runtime.h>
#include <cstdint>
#include <cstddef>

#define TGT 256
#define BSZ 8
#define EDIM 256
#define SRCL 4096

// Intermediate X[b][t][e] (2 MB)
__device__ float g_O[BSZ * TGT * EDIM];

// SW128 swizzle: XOR 16B-chunk index bits[6:4] with row%8 bits[9:7]
#define SWZ(o) ((o) ^ (((o) >> 3) & 0x70u))

// dynamic smem (bytes): A_hi 0, A_lo 8192, B_hi 16384, B_lo 24576
#define SM_AH 0
#define SM_AL 8192
#define SM_BH 16384
#define SM_BL 24576
#define SMEM_BYTES 32768

static __device__ __forceinline__ uint32_t smem_u32(const void* p) {
    uint32_t a;
    asm("{ .reg .u64 t; cvta.to.shared.u64 t, %1; cvt.u32.u64 %0, t; }" : "=r"(a) : "l"(p));
    return a;
}
// fp32 pair -> bf16x2 hi + bf16x2 lo (2-term split)
static __device__ __forceinline__ void cvt2(float x0, float x1, uint32_t& h, uint32_t& l) {
    asm("cvt.rn.bf16x2.f32 %0, %1, %2;" : "=r"(h) : "f"(x1), "f"(x0));
    float h0 = __uint_as_float(h << 16);
    float h1 = __uint_as_float(h & 0xffff0000u);
    float r0 = x0 - h0;
    float r1 = x1 - h1;
    asm("cvt.rn.bf16x2.f32 %0, %1, %2;" : "=r"(l) : "f"(r1), "f"(r0));
}
static __device__ __forceinline__ void sts64(uint32_t addr, uint32_t a, uint32_t b) {
    asm volatile("st.shared.v2.b32 [%0], {%1, %2};" :: "r"(addr), "r"(a), "r"(b) : "memory");
}
static __device__ __forceinline__ void ldsm_x4(uint32_t& r0, uint32_t& r1, uint32_t& r2,
                                               uint32_t& r3, uint32_t addr) {
    asm volatile("ldmatrix.sync.aligned.m8n8.x4.shared.b16 {%0,%1,%2,%3}, [%4];"
                 : "=r"(r0), "=r"(r1), "=r"(r2), "=r"(r3) : "r"(addr));
}
static __device__ __forceinline__ void ldsm_x2(uint32_t& r0, uint32_t& r1, uint32_t addr) {
    asm volatile("ldmatrix.sync.aligned.m8n8.x2.shared.b16 {%0,%1}, [%2];"
                 : "=r"(r0), "=r"(r1) : "r"(addr));
}
static __device__ __forceinline__ void ldsm_x2t(uint32_t& r0, uint32_t& r1, uint32_t addr) {
    asm volatile("ldmatrix.sync.aligned.m8n8.x2.trans.shared.b16 {%0,%1}, [%2];"
                 : "=r"(r0), "=r"(r1) : "r"(addr));
}
static __device__ __forceinline__ void mma_bf16(float& c0, float& c1, float& c2, float& c3,
                                                uint32_t a0, uint32_t a1, uint32_t a2,
                                                uint32_t a3, uint32_t b0, uint32_t b1) {
    asm volatile(
        "mma.sync.aligned.m16n8k16.row.col.f32.bf16.bf16.f32 "
        "{%0,%1,%2,%3}, {%4,%5,%6,%7}, {%8,%9}, {%0,%1,%2,%3};"
        : "+f"(c0), "+f"(c1), "+f"(c2), "+f"(c3)
        : "r"(a0), "r"(a1), "r"(a2), "r"(a3), "r"(b0), "r"(b1));
}

// MODE 0: X_b[64x64 tile] = mask_b[64 x 4096] @ value_b[4096 x 64]  (+ fused weights copy)
//         A K-major (mask rows), B gathered [k][n] (trans ldmatrix), out -> g_O
// MODE 1: out[64x64 tile] = X_b[64 x 256] @ W^T[256 x 64] + bias
//         A K-major (g_O), B = W rows [n][k] K-major (non-trans ldmatrix)
template <int MODE>
__global__ void __launch_bounds__(256) mma_gemm(
    const float* __restrict__ Asrc, const float* __restrict__ Bsrc,
    const float* __restrict__ bias, float* __restrict__ outp,
    float* __restrict__ weights)
{
    extern __shared__ char smem[];
    const uint32_t sb = smem_u32(smem);
    const int tid  = threadIdx.x;
    const int wid  = tid >> 5;
    const int lane = tid & 31;
    const int b    = blockIdx.z;
    const int m0   = blockIdx.y * 64;
    const int n0   = blockIdx.x * 64;
    const int wm   = wid & 1;        // 2 warps in M
    const int wn   = wid >> 1;       // 4 warps in N
    constexpr int K  = (MODE == 0) ? SRCL : EDIM;
    constexpr int NC = K / 64;

    const int rA = tid >> 4;     // 0..15 (row within 16-row group for loads)
    const int c4 = tid & 15;     // float4 column

    const float* Ag = ((MODE == 0) ? Asrc : (const float*)g_O) + ((size_t)b * TGT + m0) * K;

    float acc[2][2][4];
#pragma unroll
    for (int i = 0; i < 2; i++)
#pragma unroll
        for (int j = 0; j < 2; j++)
#pragma unroll
            for (int q = 0; q < 4; q++) acc[i][j][q] = 0.f;

    float4 aR[4], bR[4];

    // ---- prologue: load chunk 0 ----
    {
        const int k0 = 0;
        const bool docopy = (MODE == 0) && ((k0 >> 10) == (int)blockIdx.x);
#pragma unroll
        for (int j = 0; j < 4; ++j) {
            int row = j * 16 + rA;
            aR[j] = *(const float4*)(Ag + (size_t)row * K + k0 + c4 * 4);
            if (MODE == 0 && docopy)
                *(float4*)(weights + ((size_t)b * TGT + m0 + row) * SRCL + k0 + c4 * 4) = aR[j];
            if (MODE == 0)
                bR[j] = *(const float4*)(Bsrc + (size_t)(k0 + row) * (BSZ * EDIM) + b * EDIM + n0 + c4 * 4);
            else
                bR[j] = *(const float4*)(Bsrc + (size_t)(n0 + row) * EDIM + k0 + c4 * 4);
        }
    }

#pragma unroll 1
    for (int c = 0; c < NC; ++c) {
        // ---- stage: convert + store to smem ----
#pragma unroll
        for (int j = 0; j < 4; ++j) {
            int row = j * 16 + rA;
            uint32_t off = SWZ((uint32_t)(row * 128 + c4 * 8));
            uint32_t h0, l0, h1, l1;
            cvt2(aR[j].x, aR[j].y, h0, l0);
            cvt2(aR[j].z, aR[j].w, h1, l1);
            sts64(sb + SM_AH + off, h0, h1);
            sts64(sb + SM_AL + off, l0, l1);
            cvt2(bR[j].x, bR[j].y, h0, l0);
            cvt2(bR[j].z, bR[j].w, h1, l1);
            sts64(sb + SM_BH + off, h0, h1);
            sts64(sb + SM_BL + off, l0, l1);
        }
        __syncthreads();

        // ---- prefetch next chunk (LDGs overlap the MMA block below) ----
        if (c + 1 < NC) {
            const int k0 = (c + 1) * 64;
            const bool docopy = (MODE == 0) && ((k0 >> 10) == (int)blockIdx.x);
#pragma unroll
            for (int j = 0; j < 4; ++j) {
                int row = j * 16 + rA;
                aR[j] = *(const float4*)(Ag + (size_t)row * K + k0 + c4 * 4);
                if (MODE == 0 && docopy)
                    *(float4*)(weights + ((size_t)b * TGT + m0 + row) * SRCL + k0 + c4 * 4) = aR[j];
                if (MODE == 0)
                    bR[j] = *(const float4*)(Bsrc + (size_t)(k0 + row) * (BSZ * EDIM) + b * EDIM + n0 + c4 * 4);
                else
                    bR[j] = *(const float4*)(Bsrc + (size_t)(n0 + row) * EDIM + k0 + c4 * 4);
            }
        }

        // ---- MMA over the staged chunk: 4 k16 steps ----
        const int r16 = lane & 15;
        const int hA  = lane >> 4;
#pragma unroll
        for (int kk = 0; kk < 4; ++kk) {
            uint32_t ah[2][4], al[2][4];
#pragma unroll
            for (int mi = 0; mi < 2; ++mi) {
                uint32_t byteoff =
                    SWZ((uint32_t)((wm * 32 + mi * 16 + r16) * 128 + kk * 32 + hA * 16));
                ldsm_x4(ah[mi][0], ah[mi][1], ah[mi][2], ah[mi][3], sb + SM_AH + byteoff);
                ldsm_x4(al[mi][0], al[mi][1], al[mi][2], al[mi][3], sb + SM_AL + byteoff);
            }
            uint32_t bh[2][2], bl[2][2];
#pragma unroll
            for (int j = 0; j < 2; ++j) {
                uint32_t byteoff;
                if (MODE == 0) {
                    // B stored [k][n]: trans load, rows = k
                    byteoff = SWZ((uint32_t)((kk * 16 + r16) * 128 + (wn * 16 + j * 8) * 2));
                    ldsm_x2t(bh[j][0], bh[j][1], sb + SM_BH + byteoff);
                    ldsm_x2t(bl[j][0], bl[j][1], sb + SM_BL + byteoff);
                } else {
                    // B stored [n][k]: non-trans, rows = n
                    int r8 = lane & 7, hb = (lane >> 3) & 1;
                    byteoff = SWZ((uint32_t)((wn * 16 + j * 8 + r8) * 128 + kk * 32 + hb * 16));
                    ldsm_x2(bh[j][0], bh[j][1], sb + SM_BH + byteoff);
                    ldsm_x2(bl[j][0], bl[j][1], sb + SM_BL + byteoff);
                }
            }
#pragma unroll
            for (int mi = 0; mi < 2; ++mi)
#pragma unroll
                for (int j = 0; j < 2; ++j) {
                    mma_bf16(acc[mi][j][0], acc[mi][j][1], acc[mi][j][2], acc[mi][j][3],
                             ah[mi][0], ah[mi][1], ah[mi][2], ah[mi][3], bh[j][0], bh[j][1]);
                    mma_bf16(acc[mi][j][0], acc[mi][j][1], acc[mi][j][2], acc[mi][j][3],
                             ah[mi][0], ah[mi][1], ah[mi][2], ah[mi][3], bl[j][0], bl[j][1]);
                    mma_bf16(acc[mi][j][0], acc[mi][j][1], acc[mi][j][2], acc[mi][j][3],
                             al[mi][0], al[mi][1], al[mi][2], al[mi][3], bh[j][0], bh[j][1]);
                }
        }
        __syncthreads();
    }

    // ---- epilogue ----
    const int quad = lane >> 2;
    const int qt   = lane & 3;
#pragma unroll
    for (int mi = 0; mi < 2; ++mi)
#pragma unroll
        for (int j = 0; j < 2; ++j) {
            int row = m0 + wm * 32 + mi * 16 + quad;
            int col = n0 + wn * 16 + j * 8 + qt * 2;
            if (MODE == 0) {
                float* o0 = g_O + ((size_t)b * TGT + row) * EDIM + col;
                *(float2*)o0 = make_float2(acc[mi][j][0], acc[mi][j][1]);
                *(float2*)(o0 + 8 * EDIM) = make_float2(acc[mi][j][2], acc[mi][j][3]);
            } else {
                float2 bb = *(const float2*)(bias + col);
                float* o0 = outp + ((size_t)row * BSZ + b) * EDIM + col;
                *(float2*)o0 = make_float2(acc[mi][j][0] + bb.x, acc[mi][j][1] + bb.y);
                *(float2*)(outp + ((size_t)(row + 8) * BSZ + b) * EDIM + col) =
                    make_float2(acc[mi][j][2] + bb.x, acc[mi][j][3] + bb.y);
            }
        }
}

extern "C" void kernel_launch(void* const* d_in, const int* in_sizes, int n_in,
                              void* d_out, int out_size) {
    const float* value = (const float*)d_in[2];
    const float* mask  = (const float*)d_in[3];
    const float* W     = (const float*)d_in[4];
    const float* bias  = (const float*)d_in[5];
    float* out = (float*)d_out;

    float* attn_out = out;                               // (TGT, BSZ, E)
    float* weights  = out + (size_t)TGT * BSZ * EDIM;    // (BSZ, TGT, SRC)

    cudaFuncSetAttribute(mma_gemm<0>, cudaFuncAttributeMaxDynamicSharedMemorySize, SMEM_BYTES);
    cudaFuncSetAttribute(mma_gemm<1>, cudaFuncAttributeMaxDynamicSharedMemorySize, SMEM_BYTES);

    dim3 grid(4, 4, BSZ);   // 128 CTAs
    // GEMM1: X = mask @ value (per batch), fused attn_weights copy
    mma_gemm<0><<<grid, 256, SMEM_BYTES>>>(mask, value, nullptr, nullptr, weights);
    // GEMM2: out = X @ W^T + bias
    mma_gemm<1><<<grid, 256, SMEM_BYTES>>>(nullptr, W, bias, attn_out, nullptr);
}

// round 5
// speedup vs baseline: 4.3839x; 1.4368x over previous
#include <cuda_runtime.h>
#include <cstdint>
#include <cstddef>

#define TGT 256
#define BSZ 8
#define EDIM 256
#define SRCL 4096
#define PARTSZ (BSZ * TGT * EDIM)

// Split-K partials for GEMM1 (2 x 2MB)
__device__ float g_O[2 * PARTSZ];

// SW128 swizzle
#define SWZ(o) ((o) ^ (((o) >> 3) & 0x70u))

// per-buffer smem layout (bytes): A_hi 0, A_lo 8192, B_hi 16384, B_lo 24576
#define SM_AH 0
#define SM_AL 8192
#define SM_BH 16384
#define SM_BL 24576
#define BUF_BYTES 32768
#define SMEM_BYTES (2 * BUF_BYTES)

static __device__ __forceinline__ uint32_t smem_u32(const void* p) {
    uint32_t a;
    asm("{ .reg .u64 t; cvta.to.shared.u64 t, %1; cvt.u32.u64 %0, t; }" : "=r"(a) : "l"(p));
    return a;
}
// fp32 pair -> bf16x2 hi + bf16x2 lo (2-term split)
static __device__ __forceinline__ void cvt2(float x0, float x1, uint32_t& h, uint32_t& l) {
    asm("cvt.rn.bf16x2.f32 %0, %1, %2;" : "=r"(h) : "f"(x1), "f"(x0));
    float h0 = __uint_as_float(h << 16);
    float h1 = __uint_as_float(h & 0xffff0000u);
    float r0 = x0 - h0;
    float r1 = x1 - h1;
    asm("cvt.rn.bf16x2.f32 %0, %1, %2;" : "=r"(l) : "f"(r1), "f"(r0));
}
static __device__ __forceinline__ void sts64(uint32_t addr, uint32_t a, uint32_t b) {
    asm volatile("st.shared.v2.b32 [%0], {%1, %2};" :: "r"(addr), "r"(a), "r"(b) : "memory");
}
static __device__ __forceinline__ void ldsm_x4(uint32_t& r0, uint32_t& r1, uint32_t& r2,
                                               uint32_t& r3, uint32_t addr) {
    asm volatile("ldmatrix.sync.aligned.m8n8.x4.shared.b16 {%0,%1,%2,%3}, [%4];"
                 : "=r"(r0), "=r"(r1), "=r"(r2), "=r"(r3) : "r"(addr));
}
static __device__ __forceinline__ void ldsm_x2(uint32_t& r0, uint32_t& r1, uint32_t addr) {
    asm volatile("ldmatrix.sync.aligned.m8n8.x2.shared.b16 {%0,%1}, [%2];"
                 : "=r"(r0), "=r"(r1) : "r"(addr));
}
static __device__ __forceinline__ void ldsm_x2t(uint32_t& r0, uint32_t& r1, uint32_t addr) {
    asm volatile("ldmatrix.sync.aligned.m8n8.x2.trans.shared.b16 {%0,%1}, [%2];"
                 : "=r"(r0), "=r"(r1) : "r"(addr));
}
static __device__ __forceinline__ void mma_bf16(float& c0, float& c1, float& c2, float& c3,
                                                uint32_t a0, uint32_t a1, uint32_t a2,
                                                uint32_t a3, uint32_t b0, uint32_t b1) {
    asm volatile(
        "mma.sync.aligned.m16n8k16.row.col.f32.bf16.bf16.f32 "
        "{%0,%1,%2,%3}, {%4,%5,%6,%7}, {%8,%9}, {%0,%1,%2,%3};"
        : "+f"(c0), "+f"(c1), "+f"(c2), "+f"(c3)
        : "r"(a0), "r"(a1), "r"(a2), "r"(a3), "r"(b0), "r"(b1));
}

// MODE 0: partial X_b[64x64 tile] over K-half = mask_b @ value_b  (+ fused weights copy)
//         blockIdx.z = b*2 + ks (split-K). Out -> g_O[ks].
// MODE 1: out[64x64 tile] = (X0+X1)_b[64 x 256] @ W^T[256 x 64] + bias
template <int MODE>
__global__ void __launch_bounds__(256, 2) mma_gemm(
    const float* __restrict__ Asrc, const float* __restrict__ Bsrc,
    const float* __restrict__ bias, float* __restrict__ outp,
    float* __restrict__ weights)
{
    extern __shared__ char smem[];
    const uint32_t sb = smem_u32(smem);
    const int tid  = threadIdx.x;
    const int wid  = tid >> 5;
    const int lane = tid & 31;
    const int b    = (MODE == 0) ? (blockIdx.z >> 1) : blockIdx.z;
    const int ks   = (MODE == 0) ? (blockIdx.z & 1) : 0;
    const int m0   = blockIdx.y * 64;
    const int n0   = blockIdx.x * 64;
    const int wm   = wid & 1;
    const int wn   = wid >> 1;
    constexpr int K   = (MODE == 0) ? SRCL : EDIM;       // full K (A row stride)
    constexpr int KC  = (MODE == 0) ? (SRCL / 2) : EDIM; // K covered by this CTA
    constexpr int NC  = KC / 64;
    const int kbase = ks * KC;

    const int rA = tid >> 4;     // 0..15
    const int c4 = tid & 15;

    const float* Ag = ((MODE == 0) ? Asrc : (const float*)g_O) + ((size_t)b * TGT + m0) * K;

    float acc[2][2][4];
#pragma unroll
    for (int i = 0; i < 2; i++)
#pragma unroll
        for (int j = 0; j < 2; j++)
#pragma unroll
            for (int q = 0; q < 4; q++) acc[i][j][q] = 0.f;

    float4 aR[4], bR[4];

    // load one chunk into registers (global k offset = kbase + k0)
    auto load_chunk = [&](int k0) {
        const bool docopy = (MODE == 0) && (((k0 >> 9) & 3) == (int)blockIdx.x);
#pragma unroll
        for (int j = 0; j < 4; ++j) {
            int row = j * 16 + rA;
            aR[j] = *(const float4*)(Ag + (size_t)row * K + kbase + k0 + c4 * 4);
            if (MODE == 0) {
                if (docopy)
                    *(float4*)(weights + ((size_t)b * TGT + m0 + row) * SRCL + kbase + k0 + c4 * 4) = aR[j];
                bR[j] = *(const float4*)(Bsrc + (size_t)(kbase + k0 + row) * (BSZ * EDIM) + b * EDIM + n0 + c4 * 4);
            } else {
                // A for MODE1 comes via Ag (g_O part 0); add part 1 here
                float4 a2 = *(const float4*)(Ag + PARTSZ + (size_t)row * K + k0 + c4 * 4);
                aR[j].x += a2.x; aR[j].y += a2.y; aR[j].z += a2.z; aR[j].w += a2.w;
                bR[j] = *(const float4*)(Bsrc + (size_t)(n0 + row) * EDIM + k0 + c4 * 4);
            }
        }
    };

    load_chunk(0);

#pragma unroll 1
    for (int c = 0; c < NC; ++c) {
        const uint32_t bufb = sb + (uint32_t)(c & 1) * BUF_BYTES;
        // ---- stage: convert + store to smem buffer (c & 1) ----
#pragma unroll
        for (int j = 0; j < 4; ++j) {
            int row = j * 16 + rA;
            uint32_t off = SWZ((uint32_t)(row * 128 + c4 * 8));
            uint32_t h0, l0, h1, l1;
            cvt2(aR[j].x, aR[j].y, h0, l0);
            cvt2(aR[j].z, aR[j].w, h1, l1);
            sts64(bufb + SM_AH + off, h0, h1);
            sts64(bufb + SM_AL + off, l0, l1);
            cvt2(bR[j].x, bR[j].y, h0, l0);
            cvt2(bR[j].z, bR[j].w, h1, l1);
            sts64(bufb + SM_BH + off, h0, h1);
            sts64(bufb + SM_BL + off, l0, l1);
        }
        __syncthreads();   // single barrier per chunk (double buffering)

        // ---- prefetch next chunk into registers ----
        if (c + 1 < NC) load_chunk((c + 1) * 64);

        // ---- MMA over staged chunk ----
        const int r16 = lane & 15;
        const int hA  = lane >> 4;
#pragma unroll
        for (int kk = 0; kk < 4; ++kk) {
            uint32_t ah[2][4], al[2][4];
#pragma unroll
            for (int mi = 0; mi < 2; ++mi) {
                uint32_t byteoff =
                    SWZ((uint32_t)((wm * 32 + mi * 16 + r16) * 128 + kk * 32 + hA * 16));
                ldsm_x4(ah[mi][0], ah[mi][1], ah[mi][2], ah[mi][3], bufb + SM_AH + byteoff);
                ldsm_x4(al[mi][0], al[mi][1], al[mi][2], al[mi][3], bufb + SM_AL + byteoff);
            }
            uint32_t bh[2][2], bl[2][2];
#pragma unroll
            for (int j = 0; j < 2; ++j) {
                if (MODE == 0) {
                    uint32_t byteoff =
                        SWZ((uint32_t)((kk * 16 + r16) * 128 + (wn * 16 + j * 8) * 2));
                    ldsm_x2t(bh[j][0], bh[j][1], bufb + SM_BH + byteoff);
                    ldsm_x2t(bl[j][0], bl[j][1], bufb + SM_BL + byteoff);
                } else {
                    int r8 = lane & 7, hb = (lane >> 3) & 1;
                    uint32_t byteoff =
                        SWZ((uint32_t)((wn * 16 + j * 8 + r8) * 128 + kk * 32 + hb * 16));
                    ldsm_x2(bh[j][0], bh[j][1], bufb + SM_BH + byteoff);
                    ldsm_x2(bl[j][0], bl[j][1], bufb + SM_BL + byteoff);
                }
            }
#pragma unroll
            for (int mi = 0; mi < 2; ++mi)
#pragma unroll
                for (int j = 0; j < 2; ++j) {
                    mma_bf16(acc[mi][j][0], acc[mi][j][1], acc[mi][j][2], acc[mi][j][3],
                             ah[mi][0], ah[mi][1], ah[mi][2], ah[mi][3], bh[j][0], bh[j][1]);
                    mma_bf16(acc[mi][j][0], acc[mi][j][1], acc[mi][j][2], acc[mi][j][3],
                             ah[mi][0], ah[mi][1], ah[mi][2], ah[mi][3], bl[j][0], bl[j][1]);
                    mma_bf16(acc[mi][j][0], acc[mi][j][1], acc[mi][j][2], acc[mi][j][3],
                             al[mi][0], al[mi][1], al[mi][2], al[mi][3], bh[j][0], bh[j][1]);
                }
        }
    }

    // ---- epilogue ----
    const int quad = lane >> 2;
    const int qt   = lane & 3;
#pragma unroll
    for (int mi = 0; mi < 2; ++mi)
#pragma unroll
        for (int j = 0; j < 2; ++j) {
            int row = m0 + wm * 32 + mi * 16 + quad;
            int col = n0 + wn * 16 + j * 8 + qt * 2;
            if (MODE == 0) {
                float* o0 = g_O + (size_t)ks * PARTSZ + ((size_t)b * TGT + row) * EDIM + col;
                *(float2*)o0 = make_float2(acc[mi][j][0], acc[mi][j][1]);
                *(float2*)(o0 + 8 * EDIM) = make_float2(acc[mi][j][2], acc[mi][j][3]);
            } else {
                float2 bb = *(const float2*)(bias + col);
                *(float2*)(outp + ((size_t)row * BSZ + b) * EDIM + col) =
                    make_float2(acc[mi][j][0] + bb.x, acc[mi][j][1] + bb.y);
                *(float2*)(outp + ((size_t)(row + 8) * BSZ + b) * EDIM + col) =
                    make_float2(acc[mi][j][2] + bb.x, acc[mi][j][3] + bb.y);
            }
        }
}

extern "C" void kernel_launch(void* const* d_in, const int* in_sizes, int n_in,
                              void* d_out, int out_size) {
    const float* value = (const float*)d_in[2];
    const float* mask  = (const float*)d_in[3];
    const float* W     = (const float*)d_in[4];
    const float* bias  = (const float*)d_in[5];
    float* out = (float*)d_out;

    float* attn_out = out;                               // (TGT, BSZ, E)
    float* weights  = out + (size_t)TGT * BSZ * EDIM;    // (BSZ, TGT, SRC)

    cudaFuncSetAttribute(mma_gemm<0>, cudaFuncAttributeMaxDynamicSharedMemorySize, SMEM_BYTES);
    cudaFuncSetAttribute(mma_gemm<1>, cudaFuncAttributeMaxDynamicSharedMemorySize, SMEM_BYTES);

    // GEMM1: split-K=2 partials; 256 CTAs (2/SM). Fused weights copy.
    dim3 grid1(4, 4, BSZ * 2);
    mma_gemm<0><<<grid1, 256, SMEM_BYTES>>>(mask, value, nullptr, nullptr, weights);
    // GEMM2: out = (X0+X1) @ W^T + bias; 128 CTAs.
    dim3 grid2(4, 4, BSZ);
    mma_gemm<1><<<grid2, 256, SMEM_BYTES>>>(nullptr, W, bias, attn_out, nullptr);
}